// round 5
// baseline (speedup 1.0000x reference)
#include <cuda_runtime.h>
#include <math.h>

#define TOK    8192      // B*S
#define DM     1024
#define S_LEN  2048
#define NH     16
#define DK     64
#define QKV_N  3072
#define ST_STRIDE 65

// Scratch (module-static device memory: allowed; no runtime allocation)
__device__ float g_qkv [ (size_t)TOK * QKV_N ];   // [token][3*1024]  (q|k|v, each [h][d])
__device__ float g_attn[ (size_t)TOK * DM    ];   // attention output, [token][h*64+d]

// ---------------------------------------------------------------------------
// Tiled fp32 SGEMM: C[M,N] = A[M,K] @ B[K,N] + bias[N]
// BM=BN=128, BK=8, 256 threads, 8x8 per thread.
// Requires M%128==0, N%128==0, K%8==0 (true for all shapes here).
// ---------------------------------------------------------------------------
__global__ __launch_bounds__(256) void sgemm_bias_kernel(
    const float* __restrict__ A, const float* __restrict__ B,
    const float* __restrict__ bias, float* __restrict__ C,
    int M, int N, int K)
{
    __shared__ float As[8][128];   // transposed A tile: As[k][m]
    __shared__ float Bs[8][128];   // Bs[k][n]

    const int tid = threadIdx.x;
    const int tx  = tid & 15;      // 0..15 (col group)
    const int ty  = tid >> 4;      // 0..15 (row group)

    const int a_row = tid >> 1;          // 0..127
    const int a_col = (tid & 1) << 2;    // 0 or 4
    const int b_row = tid >> 5;          // 0..7
    const int b_col = (tid & 31) << 2;   // 0..124 step 4

    const float* Ab = A + (size_t)(blockIdx.y * 128) * K;
    const float* Bb = B + blockIdx.x * 128;

    float acc[8][8];
    #pragma unroll
    for (int i = 0; i < 8; i++)
        #pragma unroll
        for (int j = 0; j < 8; j++) acc[i][j] = 0.0f;

    for (int k0 = 0; k0 < K; k0 += 8) {
        float4 av = *(const float4*)(Ab + (size_t)a_row * K + k0 + a_col);
        As[a_col + 0][a_row] = av.x;
        As[a_col + 1][a_row] = av.y;
        As[a_col + 2][a_row] = av.z;
        As[a_col + 3][a_row] = av.w;
        *(float4*)(&Bs[b_row][b_col]) =
            *(const float4*)(Bb + (size_t)(k0 + b_row) * N + b_col);
        __syncthreads();

        #pragma unroll
        for (int k = 0; k < 8; k++) {
            float a_frag[8], b_frag[8];
            *(float4*)&a_frag[0] = *(const float4*)&As[k][ty * 8];
            *(float4*)&a_frag[4] = *(const float4*)&As[k][ty * 8 + 4];
            *(float4*)&b_frag[0] = *(const float4*)&Bs[k][tx * 8];
            *(float4*)&b_frag[4] = *(const float4*)&Bs[k][tx * 8 + 4];
            #pragma unroll
            for (int i = 0; i < 8; i++)
                #pragma unroll
                for (int j = 0; j < 8; j++)
                    acc[i][j] += a_frag[i] * b_frag[j];
        }
        __syncthreads();
    }

    const int crow = blockIdx.y * 128 + ty * 8;
    const int ccol = blockIdx.x * 128 + tx * 8;
    #pragma unroll
    for (int i = 0; i < 8; i++) {
        #pragma unroll
        for (int jv = 0; jv < 8; jv += 4) {
            float4 o;
            o.x = acc[i][jv + 0] + bias[ccol + jv + 0];
            o.y = acc[i][jv + 1] + bias[ccol + jv + 1];
            o.z = acc[i][jv + 2] + bias[ccol + jv + 2];
            o.w = acc[i][jv + 3] + bias[ccol + jv + 3];
            *(float4*)(C + (size_t)(crow + i) * N + ccol + jv) = o;
        }
    }
}

// ---------------------------------------------------------------------------
// Flash attention (fp32, online softmax) with relative position bias.
// One block per (q_tile of 64, head, batch). 256 threads, 4x4 micro-tiles.
// Dynamic smem layout (floats):
//   Qt [64][64]  Qt[d][r]        4096
//   Ks [64][64]  Ks[d][c]        4096
//   Vs [64][64]  Vs[c][d]        4096
//   St [64][65]  St[c*65 + r]    4160   (scores/probs, transposed, padded)
//   escale[64], invl[64], bias_s[128]
// ---------------------------------------------------------------------------
#define ATTN_SMEM_FLOATS (4096*3 + 64*ST_STRIDE + 64 + 64 + 128)
#define ATTN_SMEM_BYTES  (ATTN_SMEM_FLOATS * 4)

extern __shared__ float attn_smem[];

__global__ __launch_bounds__(256) void attn_kernel(const float* __restrict__ rel_bias)
{
    float* Qt       = attn_smem;
    float* Ks       = Qt + 4096;
    float* Vs       = Ks + 4096;
    float* St       = Vs + 4096;
    float* escale_s = St + 64 * ST_STRIDE;
    float* invl_s   = escale_s + 64;
    float* bias_s   = invl_s + 64;

    const int tid = threadIdx.x;
    const int tx  = tid & 15;     // col group (keys / dims)
    const int ty  = tid >> 4;     // row group (queries)

    const int q0   = blockIdx.x * 64;       // query base within sequence
    const int h    = blockIdx.y;
    const int b    = blockIdx.z;
    const int t0   = b * S_LEN + q0;        // global token of first query
    const int tb0  = b * S_LEN;
    const int qoff = h * DK;

    // Load Q tile, transposed: Qt[d][r]
    #pragma unroll
    for (int it = 0; it < 4; it++) {
        int flat = tid + it * 256;          // float4 index 0..1023
        int r  = flat >> 4;
        int d0 = (flat & 15) << 2;
        float4 v = *(const float4*)(g_qkv + (size_t)(t0 + r) * QKV_N + qoff + d0);
        Qt[(d0 + 0) * 64 + r] = v.x;
        Qt[(d0 + 1) * 64 + r] = v.y;
        Qt[(d0 + 2) * 64 + r] = v.z;
        Qt[(d0 + 3) * 64 + r] = v.w;
    }

    float o[4][4];
    #pragma unroll
    for (int i = 0; i < 4; i++)
        #pragma unroll
        for (int j = 0; j < 4; j++) o[i][j] = 0.0f;

    float m_r = -1e30f, l_r = 0.0f;   // used by tid<64 only

    for (int j0 = 0; j0 < S_LEN; j0 += 64) {
        __syncthreads();   // previous iteration's reads of Ks/Vs/St complete

        // Load K (transposed) and V tiles
        #pragma unroll
        for (int it = 0; it < 4; it++) {
            int flat = tid + it * 256;
            int c  = flat >> 4;
            int d0 = (flat & 15) << 2;
            const float* base = g_qkv + (size_t)(tb0 + j0 + c) * QKV_N + qoff;
            float4 kv = *(const float4*)(base + 1024 + d0);
            Ks[(d0 + 0) * 64 + c] = kv.x;
            Ks[(d0 + 1) * 64 + c] = kv.y;
            Ks[(d0 + 2) * 64 + c] = kv.z;
            Ks[(d0 + 3) * 64 + c] = kv.w;
            float4 vv = *(const float4*)(base + 2048 + d0);
            *(float4*)&Vs[c * 64 + d0] = vv;
        }
        // Stage the 127 distinct bias diagonals for this (q-tile, k-tile) pair
        if (tid < 127) {
            int rel = (q0 - j0) + (tid - 63) + 1024;
            rel = min(max(rel, 0), 2 * 1024);
            bias_s[tid] = __ldg(rel_bias + rel * NH + h);
        }
        __syncthreads();

        // S = Q @ K^T  (4x4 per thread over the d loop)
        float s[4][4];
        #pragma unroll
        for (int i = 0; i < 4; i++)
            #pragma unroll
            for (int j = 0; j < 4; j++) s[i][j] = 0.0f;
        #pragma unroll 8
        for (int d = 0; d < 64; d++) {
            float4 aq = *(const float4*)&Qt[d * 64 + ty * 4];
            float4 bk = *(const float4*)&Ks[d * 64 + tx * 4];
            s[0][0] += aq.x * bk.x; s[0][1] += aq.x * bk.y; s[0][2] += aq.x * bk.z; s[0][3] += aq.x * bk.w;
            s[1][0] += aq.y * bk.x; s[1][1] += aq.y * bk.y; s[1][2] += aq.y * bk.z; s[1][3] += aq.y * bk.w;
            s[2][0] += aq.z * bk.x; s[2][1] += aq.z * bk.y; s[2][2] += aq.z * bk.z; s[2][3] += aq.z * bk.w;
            s[3][0] += aq.w * bk.x; s[3][1] += aq.w * bk.y; s[3][2] += aq.w * bk.z; s[3][3] += aq.w * bk.w;
        }
        // Scale + bias, store transposed: St[c][r]
        #pragma unroll
        for (int jj = 0; jj < 4; jj++) {
            #pragma unroll
            for (int ii = 0; ii < 4; ii++) {
                int bidx = (ty * 4 + ii) - (tx * 4 + jj) + 63;   // 0..126
                St[(tx * 4 + jj) * ST_STRIDE + ty * 4 + ii] =
                    0.125f * s[ii][jj] + bias_s[bidx];
            }
        }
        __syncthreads();

        // Online softmax: one thread per query row
        if (tid < 64) {
            const int r = tid;
            float tmax = -1e30f;
            #pragma unroll 8
            for (int c = 0; c < 64; c++)
                tmax = fmaxf(tmax, St[c * ST_STRIDE + r]);
            float m_new = fmaxf(m_r, tmax);
            float esc   = __expf(m_r - m_new);
            float rs = 0.0f;
            #pragma unroll 8
            for (int c = 0; c < 64; c++) {
                float p = __expf(St[c * ST_STRIDE + r] - m_new);
                St[c * ST_STRIDE + r] = p;
                rs += p;
            }
            l_r = l_r * esc + rs;
            m_r = m_new;
            escale_s[r] = esc;
        }
        __syncthreads();

        // Rescale O, accumulate P @ V
        float esc_i[4];
        #pragma unroll
        for (int ii = 0; ii < 4; ii++) esc_i[ii] = escale_s[ty * 4 + ii];
        #pragma unroll
        for (int ii = 0; ii < 4; ii++)
            #pragma unroll
            for (int jj = 0; jj < 4; jj++) o[ii][jj] *= esc_i[ii];

        #pragma unroll 8
        for (int c = 0; c < 64; c++) {
            const float* Sc = &St[c * ST_STRIDE + ty * 4];
            float p0 = Sc[0], p1 = Sc[1], p2 = Sc[2], p3 = Sc[3];
            float4 vv = *(const float4*)&Vs[c * 64 + tx * 4];
            o[0][0] += p0 * vv.x; o[0][1] += p0 * vv.y; o[0][2] += p0 * vv.z; o[0][3] += p0 * vv.w;
            o[1][0] += p1 * vv.x; o[1][1] += p1 * vv.y; o[1][2] += p1 * vv.z; o[1][3] += p1 * vv.w;
            o[2][0] += p2 * vv.x; o[2][1] += p2 * vv.y; o[2][2] += p2 * vv.z; o[2][3] += p2 * vv.w;
            o[3][0] += p3 * vv.x; o[3][1] += p3 * vv.y; o[3][2] += p3 * vv.z; o[3][3] += p3 * vv.w;
        }
    }

    __syncthreads();
    if (tid < 64) invl_s[tid] = 1.0f / l_r;
    __syncthreads();

    // Normalize and write: g_attn[token][h*64 + d]
    #pragma unroll
    for (int ii = 0; ii < 4; ii++) {
        float inv = invl_s[ty * 4 + ii];
        float4 ov;
        ov.x = o[ii][0] * inv;
        ov.y = o[ii][1] * inv;
        ov.z = o[ii][2] * inv;
        ov.w = o[ii][3] * inv;
        *(float4*)(g_attn + (size_t)(t0 + ty * 4 + ii) * DM + qoff + tx * 4) = ov;
    }
}

// ---------------------------------------------------------------------------
// Launch
// ---------------------------------------------------------------------------
extern "C" void kernel_launch(void* const* d_in, const int* in_sizes, int n_in,
                              void* d_out, int out_size)
{
    const float* x        = (const float*)d_in[0];  // [8192,1024]
    const float* W_qkv    = (const float*)d_in[1];  // [1024,3072]
    const float* b_qkv    = (const float*)d_in[2];  // [3072]
    const float* W_out    = (const float*)d_in[3];  // [1024,1024]
    const float* b_out    = (const float*)d_in[4];  // [1024]
    const float* rel_bias = (const float*)d_in[5];  // [2049,16]
    float* out = (float*)d_out;                     // [8192,1024]

    float* qkv_ptr = nullptr;
    float* attn_ptr = nullptr;
    cudaGetSymbolAddress((void**)&qkv_ptr,  g_qkv);
    cudaGetSymbolAddress((void**)&attn_ptr, g_attn);

    cudaFuncSetAttribute(attn_kernel,
                         cudaFuncAttributeMaxDynamicSharedMemorySize,
                         ATTN_SMEM_BYTES);

    // 1) QKV projection: [8192,1024] @ [1024,3072] + b
    {
        dim3 grid(QKV_N / 128, TOK / 128);
        sgemm_bias_kernel<<<grid, 256>>>(x, W_qkv, b_qkv, qkv_ptr,
                                         TOK, QKV_N, DM);
    }
    // 2) Attention with relative bias
    {
        dim3 grid(S_LEN / 64, NH, 4);
        attn_kernel<<<grid, 256, ATTN_SMEM_BYTES>>>(rel_bias);
    }
    // 3) Output projection: [8192,1024] @ [1024,1024] + b
    {
        dim3 grid(DM / 128, TOK / 128);
        sgemm_bias_kernel<<<grid, 256>>>(attn_ptr, W_out, b_out, out,
                                         TOK, DM, DM);
    }
}